// round 16
// baseline (speedup 1.0000x reference)
#include <cuda_runtime.h>
#include <cuda_bf16.h>
#include <cuda_fp16.h>

// GINConv forward: out = segment_sum(X[ci]) @ W  ==  segment_sum((X@W)[ci])
// Kernel 1: Y = X @ W, fp16 out — exact R11 version (proven).
// Kernel 2: out = segment_sum(Y[ci]) — FULL warp per node, one uint
//           (2 halves) per lane: 128B fp16 row == 32 lanes x 4B. No
//           intra-warp divergence (one degree per warp), 1 HADD2/edge/lane,
//           8-deep gather pipeline at ~40 regs.
// (Resubmission of R15 — previous round was an infra failure, kernel unmeasured.)

#define D_FEAT 64
#define N_NODES_MAX 100000

// Scratch for Y in fp16 (12.8 MB). __device__ global: allowed (no alloc).
__device__ __align__(16) __half g_Yh[(size_t)N_NODES_MAX * D_FEAT];

// ---- packed f32x2 helpers (sm_103a) ----
__device__ __forceinline__ unsigned long long pk2(float lo, float hi) {
    unsigned long long r;
    asm("mov.b64 %0, {%1, %2};" : "=l"(r) : "f"(lo), "f"(hi));
    return r;
}
__device__ __forceinline__ void unpk2(unsigned long long v, float& lo, float& hi) {
    asm("mov.b64 {%0, %1}, %2;" : "=f"(lo), "=f"(hi) : "l"(v));
}
__device__ __forceinline__ void fma2(unsigned long long& d,
                                     unsigned long long a,
                                     unsigned long long b) {
    asm("fma.rn.f32x2 %0, %1, %2, %0;" : "+l"(d) : "l"(a), "l"(b));
}

// Packed fp16 accumulate on one 32-bit word (2 halves): a += v
__device__ __forceinline__ void hacc1(unsigned& a, const unsigned v) {
    __half2& ah = *reinterpret_cast<__half2*>(&a);
    ah = __hadd2(ah, *reinterpret_cast<const __half2*>(&v));
}

// Convert one uint (2 halves) to float2
__device__ __forceinline__ float2 h2f(const unsigned u) {
    return __half22float2(*reinterpret_cast<const __half2*>(&u));
}

// ================= Kernel 1: Y = X @ W (fp16 out) — R11 exact =============
// 64-row tile per block, 256 threads as 16x16, each thread a 4x4 micro-tile.
__global__ __launch_bounds__(256) void gemm_xw_kernel(
    const float* __restrict__ X,
    const float* __restrict__ W,
    uint2* __restrict__ Yh2,      // [n_rows * 16] uint2 (4 halves each)
    int n_rows)
{
    __shared__ __align__(16) float Xs[D_FEAT][68];               // 17.4 KB
    __shared__ __align__(16) unsigned long long Wp[D_FEAT * 32]; // 16 KB

    const int tid = threadIdx.x;
    const int ty = tid >> 4;
    const int tx = tid & 15;
    const int base = blockIdx.x * 64;

    #pragma unroll
    for (int i = tid; i < 1024; i += 256) {
        const float4 w4 = reinterpret_cast<const float4*>(W)[i];
        const int k = i >> 4, p = i & 15;
        Wp[k * 32 + 2 * p + 0] = pk2(w4.x, w4.y);
        Wp[k * 32 + 2 * p + 1] = pk2(w4.z, w4.w);
    }
    #pragma unroll
    for (int i = tid; i < 1024; i += 256) {
        const int r = i >> 4, q = i & 15;
        float4 v = make_float4(0.f, 0.f, 0.f, 0.f);
        if (base + r < n_rows)
            v = reinterpret_cast<const float4*>(X)[(size_t)(base + r) * 16 + q];
        *reinterpret_cast<float4*>(&Xs[r][q * 4]) = v;
    }
    __syncthreads();

    unsigned long long acc[4][2] = {};

    #pragma unroll 4
    for (int k = 0; k < D_FEAT; ++k) {
        const longlong2 w2 =
            reinterpret_cast<const longlong2*>(Wp + k * 32)[tx];
        #pragma unroll
        for (int j = 0; j < 4; ++j) {
            const float x = Xs[ty * 4 + j][k];
            const unsigned long long xx = pk2(x, x);
            fma2(acc[j][0], xx, (unsigned long long)w2.x);
            fma2(acc[j][1], xx, (unsigned long long)w2.y);
        }
    }

    #pragma unroll
    for (int j = 0; j < 4; ++j) {
        const int row = base + ty * 4 + j;
        if (row < n_rows) {
            float a, b, c, d;
            unpk2(acc[j][0], a, b);
            unpk2(acc[j][1], c, d);
            const __half2 h0 = __float22half2_rn(make_float2(a, b));
            const __half2 h1 = __float22half2_rn(make_float2(c, d));
            uint2 u;
            u.x = *reinterpret_cast<const unsigned*>(&h0);
            u.y = *reinterpret_cast<const unsigned*>(&h1);
            Yh2[(size_t)row * 16 + tx] = u;
        }
    }
}

// ============ Kernel 2: out = segment_sum(Y[ci]) ============
// FULL warp (32 lanes) per node; lane owns one uint (2 halves) of the 128B
// fp16 row. One degree per warp -> zero divergence. 8 broadcast ci loads +
// 8 independent LDG.32 gathers per trip; 1 HADD2 per edge per lane into 4
// independent fp16 accumulator words.
__global__ __launch_bounds__(128, 12) void gather_sum_kernel(
    const unsigned* __restrict__ Yh1,
    const int* __restrict__ rp,
    const int* __restrict__ ci,
    float2* __restrict__ out2,
    int n_nodes)
{
    const int lane = threadIdx.x & 31;
    const int wid  = threadIdx.x >> 5;           // warp within block: 0..3
    const int node = blockIdx.x * 4 + wid;
    if (node >= n_nodes) return;

    const int start = __ldg(&rp[node]);
    const int end   = __ldg(&rp[node + 1]);

    unsigned a0 = 0u, a1 = 0u, a2 = 0u, a3 = 0u; // half2 zeros

    int e = start;

    // Main: 8 edges per trip -> 8 independent gathers in flight per warp
    for (; e + 8 <= end; e += 8) {
        const int c0 = __ldg(&ci[e + 0]);
        const int c1 = __ldg(&ci[e + 1]);
        const int c2 = __ldg(&ci[e + 2]);
        const int c3 = __ldg(&ci[e + 3]);
        const int c4 = __ldg(&ci[e + 4]);
        const int c5 = __ldg(&ci[e + 5]);
        const int c6 = __ldg(&ci[e + 6]);
        const int c7 = __ldg(&ci[e + 7]);
        const unsigned v0 = __ldg(&Yh1[(size_t)c0 * 32 + lane]);
        const unsigned v1 = __ldg(&Yh1[(size_t)c1 * 32 + lane]);
        const unsigned v2 = __ldg(&Yh1[(size_t)c2 * 32 + lane]);
        const unsigned v3 = __ldg(&Yh1[(size_t)c3 * 32 + lane]);
        const unsigned v4 = __ldg(&Yh1[(size_t)c4 * 32 + lane]);
        const unsigned v5 = __ldg(&Yh1[(size_t)c5 * 32 + lane]);
        const unsigned v6 = __ldg(&Yh1[(size_t)c6 * 32 + lane]);
        const unsigned v7 = __ldg(&Yh1[(size_t)c7 * 32 + lane]);
        hacc1(a0, v0); hacc1(a1, v1); hacc1(a2, v2); hacc1(a3, v3);
        hacc1(a0, v4); hacc1(a1, v5); hacc1(a2, v6); hacc1(a3, v7);
    }

    // 4-edge chunk
    if (e + 4 <= end) {
        const int c0 = __ldg(&ci[e + 0]);
        const int c1 = __ldg(&ci[e + 1]);
        const int c2 = __ldg(&ci[e + 2]);
        const int c3 = __ldg(&ci[e + 3]);
        const unsigned v0 = __ldg(&Yh1[(size_t)c0 * 32 + lane]);
        const unsigned v1 = __ldg(&Yh1[(size_t)c1 * 32 + lane]);
        const unsigned v2 = __ldg(&Yh1[(size_t)c2 * 32 + lane]);
        const unsigned v3 = __ldg(&Yh1[(size_t)c3 * 32 + lane]);
        hacc1(a0, v0); hacc1(a1, v1); hacc1(a2, v2); hacc1(a3, v3);
        e += 4;
    }

    // Scalar tail
    for (; e < end; ++e) {
        const int c = __ldg(&ci[e]);
        hacc1(a0, __ldg(&Yh1[(size_t)c * 32 + lane]));
    }

    // Final combine in fp32
    const float2 f0 = h2f(a0);
    const float2 f1 = h2f(a1);
    const float2 f2 = h2f(a2);
    const float2 f3 = h2f(a3);

    float2 r;
    r.x = (f0.x + f1.x) + (f2.x + f3.x);
    r.y = (f0.y + f1.y) + (f2.y + f3.y);

    out2[(size_t)node * 32 + lane] = r;   // 256B contiguous per warp
}

extern "C" void kernel_launch(void* const* d_in, const int* in_sizes, int n_in,
                              void* d_out, int out_size) {
    const float* X  = (const float*)d_in[0];   // [100000, 64]
    const float* W  = (const float*)d_in[1];   // [64, 64]
    const int*   rp = (const int*)d_in[2];     // [100001]
    const int*   ci = (const int*)d_in[3];     // [1600000]
    float* out = (float*)d_out;                // [100000, 64]

    const int n_nodes = in_sizes[2] - 1;       // 100000

    __half* Yptr = nullptr;
    cudaGetSymbolAddress((void**)&Yptr, g_Yh);

    const int blocks1 = (n_nodes + 63) / 64;
    gemm_xw_kernel<<<blocks1, 256>>>(X, W, reinterpret_cast<uint2*>(Yptr),
                                     n_nodes);

    const int blocks2 = (n_nodes + 3) / 4;
    gather_sum_kernel<<<blocks2, 128>>>(
        reinterpret_cast<const unsigned*>(Yptr), rp, ci,
        reinterpret_cast<float2*>(out), n_nodes);
}